// round 14
// baseline (speedup 1.0000x reference)
#include <cuda_runtime.h>

// GAT_28295244546247 — v12: 2 CTAs per SM (256 blocks x 256 threads, RPB=16)
// for cross-CTA latency hiding; same algorithm as the 10.75us v10 otherwise.
// Analytic collapse (R0): softmax row-constant cancels => identical output rows;
// layer2 softmax exactly uniform; a2_w/a2_b have no effect.

#define NH    8
#define NBLK  256
#define RPB   16
#define NT    256
#define F_OUT 32
#define NC    4              // partial copies (fold & q-accum)

__device__ float    g_q[NH * 64];   // zero-init; reset by last exiter each replay
__device__ float    g_Z[NH];
__device__ unsigned g_arrive = 0;
__device__ unsigned g_exit   = 0;

__global__ __launch_bounds__(NT, 2) void gat_fused(
    const float* __restrict__ x,   const float* __restrict__ W1,
    const float* __restrict__ b1,  const float* __restrict__ a1w,
    const float* __restrict__ a1b, const float* __restrict__ W2,
    const float* __restrict__ b2,  float* __restrict__ out)
{
    __shared__ float W1s[64 * 65];                  // padded, conflict-free both axes
    __shared__ __align__(16) float W2s[F_OUT * 64];
    __shared__ __align__(16) float a1wjs[NH * 64];  // a1w[:,64:128]
    __shared__ __align__(16) float b1s[64];
    __shared__ __align__(16) float b2s[F_OUT];
    __shared__ __align__(16) float us[NH * 64];     // folded u [h][k]
    __shared__ float cs[NH];
    __shared__ __align__(16) float xs[RPB * 68];
    __shared__ __align__(16) float es[RPB * NH];
    __shared__ float qs4[NC][NH * 64];              // 4-copy partials
    __shared__ float qbar[64];
    __shared__ float os[64];
    __shared__ float fs[F_OUT];
    __shared__ int   s_last;

    const int t = threadIdx.x;
    const int b = blockIdx.x;
    const int g = t >> 4, u = t & 15;               // 16 rows x 16 threads/row

    // ---- phase 0: x load (1 float4/thread) + weight staging ----
    float4 x4 = ((const float4*)(x + (b * RPB + g) * 64 + u * 4))[0];
    {
        const float4* w4 = (const float4*)W1;
        #pragma unroll
        for (int r = 0; r < 4; r++) {
            int i = t + r * NT;
            float4 v = w4[i];
            int f = i >> 4, k = (i & 15) << 2;
            float* d = &W1s[f * 65 + k];
            d[0] = v.x; d[1] = v.y; d[2] = v.z; d[3] = v.w;
        }
        if (t < 128) {
            int h = t >> 4, q = t & 15;
            ((float4*)a1wjs)[h * 16 + q] = ((const float4*)a1w)[h * 32 + 16 + q];
        } else if (t < 144) {
            ((float4*)b1s)[t - 128] = ((const float4*)b1)[t - 128];
        }
        ((float4*)&xs[g * 68])[u] = x4;
    }
    __syncthreads();

    // ---- phase 1: fold v2 — W1s value read once, shared across 8 heads ----
    // t = fg*64 + k, fg in [0,4): this thread covers f = fg*16 .. fg*16+15
    {
        const int fg = t >> 6, k = t & 63;
        float acc[NH];
        #pragma unroll
        for (int h = 0; h < NH; h++) acc[h] = 0.f;
        #pragma unroll
        for (int q = 0; q < 4; q++) {               // four f-quads
            const int f0 = fg * 16 + q * 4;
            float4 ar[NH];
            #pragma unroll
            for (int h = 0; h < NH; h++)
                ar[h] = ((const float4*)&a1wjs[h * 64 + f0])[0];
            #pragma unroll
            for (int fo = 0; fo < 4; fo++) {
                float w = W1s[(f0 + fo) * 65 + k];
                #pragma unroll
                for (int h = 0; h < NH; h++) {
                    float a = (fo == 0) ? ar[h].x : (fo == 1) ? ar[h].y
                            : (fo == 2) ? ar[h].z : ar[h].w;
                    acc[h] += w * a;
                }
            }
        }
        #pragma unroll
        for (int h = 0; h < NH; h++) qs4[fg][h * 64 + k] = acc[h];
    }
    if (t < NH) {                                    // c[h] = a1b + a1wj.b1
        const float* ar = &a1wjs[t * 64];
        float s0 = 0.f, s1 = 0.f, s2 = 0.f, s3 = 0.f;
        #pragma unroll
        for (int f = 0; f < 64; f += 4) {
            s0 += ar[f + 0] * b1s[f + 0];
            s1 += ar[f + 1] * b1s[f + 1];
            s2 += ar[f + 2] * b1s[f + 2];
            s3 += ar[f + 3] * b1s[f + 3];
        }
        cs[t] = a1b[t] + (s0 + s1) + (s2 + s3);
    }
    __syncthreads();

    // ---- phase 2: tree-sum fold partials -> us (2 elements/thread) ----
    #pragma unroll
    for (int r = 0; r < 2; r++) {
        int e = t + r * NT;
        float s0 = qs4[0][e] + qs4[1][e];
        float s1 = qs4[2][e] + qs4[3][e];
        us[e] = s0 + s1;
    }
    __syncthreads();

    // ---- phase 3: scores — 16 threads/row, butterfly reduce, exp ----
    {
        float s[NH];
        #pragma unroll
        for (int h = 0; h < NH; h++) {
            float4 u4 = ((const float4*)us)[h * 16 + u];
            s[h] = u4.x * x4.x + u4.y * x4.y + u4.z * x4.z + u4.w * x4.w;
        }
        #pragma unroll
        for (int h = 0; h < NH; h++)
            s[h] += __shfl_xor_sync(0xffffffffu, s[h], 8);
        float r4[4];
        {
            const bool lo = (u & 4) == 0;
            #pragma unroll
            for (int i = 0; i < 4; i++) {
                float give = lo ? s[i + 4] : s[i];
                float got  = __shfl_xor_sync(0xffffffffu, give, 4);
                r4[i] = (lo ? s[i] : s[i + 4]) + got;
            }
        }
        float r2[2];
        {
            const bool lo = (u & 2) == 0;
            #pragma unroll
            for (int i = 0; i < 2; i++) {
                float give = lo ? r4[i + 2] : r4[i];
                float got  = __shfl_xor_sync(0xffffffffu, give, 2);
                r2[i] = (lo ? r4[i] : r4[i + 2]) + got;
            }
        }
        float rf;
        {
            const bool lo = (u & 1) == 0;
            float give = lo ? r2[1] : r2[0];
            float got  = __shfl_xor_sync(0xffffffffu, give, 1);
            rf = (lo ? r2[0] : r2[1]) + got;
        }
        if (u < NH) es[g * 8 + u] = __expf(rf + cs[u]);
    }
    __syncthreads();

    // ---- phase 4: q partial (f-parallel, 4 j-lanes, float4 es reads) ----
    {
        const int f = t & 63, l = t >> 6;
        float acc[NH];
        #pragma unroll
        for (int h = 0; h < NH; h++) acc[h] = 0.f;
        #pragma unroll
        for (int jj = l; jj < RPB; jj += 4) {
            float4 e0 = ((const float4*)&es[jj * 8])[0];
            float4 e1 = ((const float4*)&es[jj * 8])[1];
            float xv = xs[jj * 68 + f];
            acc[0] += e0.x * xv; acc[1] += e0.y * xv;
            acc[2] += e0.z * xv; acc[3] += e0.w * xv;
            acc[4] += e1.x * xv; acc[5] += e1.y * xv;
            acc[6] += e1.z * xv; acc[7] += e1.w * xv;
        }
        #pragma unroll
        for (int h = 0; h < NH; h++) qs4[l][h * 64 + f] = acc[h];
    }
    __syncthreads();

    // ---- phase 5: tree-sum + REDG publish (2 elements/thread) ----
    #pragma unroll
    for (int r = 0; r < 2; r++) {
        int e = t + r * NT;
        float s0 = qs4[0][e] + qs4[1][e];
        float s1 = qs4[2][e] + qs4[3][e];
        atomicAdd(&g_q[e], s0 + s1);
    }
    if (t < NH) {
        float z0 = 0.f, z1 = 0.f, z2 = 0.f, z3 = 0.f;
        #pragma unroll
        for (int jj = 0; jj < RPB; jj += 4) {
            z0 += es[(jj + 0) * 8 + t];
            z1 += es[(jj + 1) * 8 + t];
            z2 += es[(jj + 2) * 8 + t];
            z3 += es[(jj + 3) * 8 + t];
        }
        atomicAdd(&g_Z[t], (z0 + z1) + (z2 + z3));
    }

    // ---- grid sync; stage W2/b2 inside the poll window ----
    __threadfence();
    __syncthreads();
    if (t == 0) atomicAdd(&g_arrive, 1);
    ((float4*)W2s)[t]      = ((const float4*)W2)[t];
    ((float4*)W2s)[t + NT] = ((const float4*)W2)[t + NT];
    if (t < NH) ((float4*)b2s)[t] = ((const float4*)b2)[t];
    if (t == 0) {
        while (*(volatile unsigned*)&g_arrive < NBLK) __nanosleep(32);
    }
    __syncthreads();
    __threadfence();

    // ---- tail: qbar (t = f*4 + h2; each thread covers heads h2 and h2+4) ----
    {
        const int f = t >> 2, h2 = t & 3;
        float v = g_q[h2 * 64 + f] / g_Z[h2]
                + g_q[(h2 + 4) * 64 + f] / g_Z[h2 + 4];
        v += __shfl_xor_sync(0xffffffffu, v, 1);
        v += __shfl_xor_sync(0xffffffffu, v, 2);
        if (h2 == 0) qbar[f] = v * (1.f / NH);
    }
    __syncthreads();
    if (t == 0) s_last = (atomicAdd(&g_exit, 1) == NBLK - 1);  // g_q consumed

    {   // os[m] = elu(lrelu(W1s[m,:].qbar + b1[m])) : 4 threads/output, 16 k each
        const int m = t >> 2, kc = t & 3;
        const float* wr = &W1s[m * 65 + kc * 16];
        const float* qq = &qbar[kc * 16];
        float s0 = 0.f, s1 = 0.f, s2 = 0.f, s3 = 0.f;
        #pragma unroll
        for (int i = 0; i < 16; i += 4) {
            s0 += wr[i + 0] * qq[i + 0];
            s1 += wr[i + 1] * qq[i + 1];
            s2 += wr[i + 2] * qq[i + 2];
            s3 += wr[i + 3] * qq[i + 3];
        }
        float s = (s0 + s1) + (s2 + s3);
        s += __shfl_xor_sync(0xffffffffu, s, 1);
        s += __shfl_xor_sync(0xffffffffu, s, 2);
        if (kc == 0) {
            s += b1s[m];
            float lr = s > 0.f ? s : 0.2f * s;
            os[m] = lr > 0.f ? lr : (__expf(lr) - 1.f);
        }
    }
    __syncthreads();
    {   // fs[m] = lrelu(W2s[m,:].os + b2[m]) : 8 threads/output, 8 k each
        const int m = t >> 3, kc = t & 7;
        float4 w0 = ((const float4*)W2s)[m * 16 + kc * 2];
        float4 w1 = ((const float4*)W2s)[m * 16 + kc * 2 + 1];
        const float* o8 = &os[kc * 8];
        float s = w0.x * o8[0] + w0.y * o8[1] + w0.z * o8[2] + w0.w * o8[3]
                + w1.x * o8[4] + w1.y * o8[5] + w1.z * o8[6] + w1.w * o8[7];
        s += __shfl_xor_sync(0xffffffffu, s, 1);
        s += __shfl_xor_sync(0xffffffffu, s, 2);
        s += __shfl_xor_sync(0xffffffffu, s, 4);
        if (kc == 0) {
            s += b2s[m];
            fs[m] = s > 0.f ? s : 0.2f * s;
        }
    }
    __syncthreads();

    // ---- output: 16 rows x 32 cols per block = 128 float4 ----
    if (t < 128) {
        int f0 = (t & 7) << 2;
        float4 v = make_float4(fs[f0], fs[f0 + 1], fs[f0 + 2], fs[f0 + 3]);
        ((float4*)out)[b * 128 + t] = v;
    }

    // ---- reset for next graph replay (last exiting block; all reads done) ----
    __syncthreads();
    if (s_last) {
        g_q[t] = 0.f;
        g_q[t + NT] = 0.f;
        if (t < NH) g_Z[t] = 0.f;
        if (t == 0) { g_arrive = 0; g_exit = 0; }
    }
}

extern "C" void kernel_launch(void* const* d_in, const int* in_sizes, int n_in,
                              void* d_out, int out_size) {
    const float* x   = (const float*)d_in[0];
    const float* W1  = (const float*)d_in[1];
    const float* b1  = (const float*)d_in[2];
    const float* a1w = (const float*)d_in[3];
    const float* a1b = (const float*)d_in[4];
    const float* W2  = (const float*)d_in[5];
    const float* b2  = (const float*)d_in[6];
    // d_in[7] (a2_w), d_in[8] (a2_b): provably no effect on output.

    gat_fused<<<NBLK, NT>>>(x, W1, b1, a1w, a1b, W2, b2, (float*)d_out);
}

// round 15
// speedup vs baseline: 1.1792x; 1.1792x over previous
#include <cuda_runtime.h>

// GAT_28295244546247 — v13: exact v10 structure (best: 10.75us) with the REDG
// publish vectorized via red.global.add.v4.f32 (512 -> 128 RED ops per block;
// 4x less same-address L2 atomic contention feeding the grid sync).
// Analytic collapse (R0): softmax row-constant cancels => identical output rows;
// layer2 softmax exactly uniform; a2_w/a2_b have no effect.

#define NH    8
#define NBLK  128
#define RPB   32
#define NT    512
#define F_OUT 32

__device__ __align__(16) float g_q[NH * 64];  // zero-init; reset by last exiter
__device__ float    g_Z[NH];
__device__ unsigned g_arrive = 0;
__device__ unsigned g_exit   = 0;

__device__ __forceinline__ void red_add_v4(float* addr, float4 v) {
    asm volatile("red.global.add.v4.f32 [%0], {%1, %2, %3, %4};"
                 :: "l"(addr), "f"(v.x), "f"(v.y), "f"(v.z), "f"(v.w)
                 : "memory");
}

__global__ __launch_bounds__(NT) void gat_fused(
    const float* __restrict__ x,   const float* __restrict__ W1,
    const float* __restrict__ b1,  const float* __restrict__ a1w,
    const float* __restrict__ a1b, const float* __restrict__ W2,
    const float* __restrict__ b2,  float* __restrict__ out)
{
    __shared__ float W1s[64 * 65];                  // padded, conflict-free both axes
    __shared__ __align__(16) float W2s[F_OUT * 64];
    __shared__ __align__(16) float a1wjs[NH * 64];  // a1w[:,64:128]
    __shared__ __align__(16) float b1s[64];
    __shared__ __align__(16) float b2s[F_OUT];
    __shared__ __align__(16) float us[NH * 64];     // folded u [h][k]
    __shared__ float cs[NH];
    __shared__ __align__(16) float xs[RPB * 68];    // stride 68: float4-aligned rows
    __shared__ __align__(16) float es[RPB * NH];
    __shared__ __align__(16) float qs8[8][NH * 64]; // 8-copy partials (fold & q-accum)
    __shared__ float qbar[64];
    __shared__ float os[64];
    __shared__ float fs[F_OUT];
    __shared__ int   s_last;

    const int t = threadIdx.x;
    const int b = blockIdx.x;
    const int g = t >> 4, u = t & 15;               // 32 rows x 16 threads/row

    // ---- phase 0: x load (1 float4/thread) + weight staging ----
    float4 x4 = ((const float4*)(x + (b * RPB + g) * 64 + u * 4))[0];
    {
        const float4* w4 = (const float4*)W1;
        #pragma unroll
        for (int r = 0; r < 2; r++) {
            int i = t + r * NT;
            float4 v = w4[i];
            int f = i >> 4, k = (i & 15) << 2;
            float* d = &W1s[f * 65 + k];
            d[0] = v.x; d[1] = v.y; d[2] = v.z; d[3] = v.w;
        }
        if (t < 128) {
            int h = t >> 4, q = t & 15;
            ((float4*)a1wjs)[h * 16 + q] = ((const float4*)a1w)[h * 32 + 16 + q];
        } else if (t < 144) {
            ((float4*)b1s)[t - 128] = ((const float4*)b1)[t - 128];
        }
        ((float4*)&xs[g * 68])[u] = x4;
    }
    __syncthreads();

    // ---- phase 1: fold v2 — each W1s value read ONCE, shared across 8 heads ----
    {
        const int fg = t >> 6, k = t & 63;
        float acc[NH];
        #pragma unroll
        for (int h = 0; h < NH; h++) acc[h] = 0.f;
        #pragma unroll
        for (int q = 0; q < 2; q++) {               // two f-quads
            const int f0 = fg * 8 + q * 4;
            float4 ar[NH];                           // broadcast LDS.128 per head
            #pragma unroll
            for (int h = 0; h < NH; h++)
                ar[h] = ((const float4*)&a1wjs[h * 64 + f0])[0];
            #pragma unroll
            for (int fo = 0; fo < 4; fo++) {
                float w = W1s[(f0 + fo) * 65 + k];
                #pragma unroll
                for (int h = 0; h < NH; h++) {
                    float a = (fo == 0) ? ar[h].x : (fo == 1) ? ar[h].y
                            : (fo == 2) ? ar[h].z : ar[h].w;
                    acc[h] += w * a;
                }
            }
        }
        #pragma unroll
        for (int h = 0; h < NH; h++) qs8[fg][h * 64 + k] = acc[h];
    }
    if (t < NH) {                                    // c[h] = a1b + ar.b1 (4-acc)
        const float* ar = &a1wjs[t * 64];
        float s0 = 0.f, s1 = 0.f, s2 = 0.f, s3 = 0.f;
        #pragma unroll
        for (int f = 0; f < 64; f += 4) {
            s0 += ar[f + 0] * b1s[f + 0];
            s1 += ar[f + 1] * b1s[f + 1];
            s2 += ar[f + 2] * b1s[f + 2];
            s3 += ar[f + 3] * b1s[f + 3];
        }
        cs[t] = a1b[t] + (s0 + s1) + (s2 + s3);
    }
    __syncthreads();

    // ---- phase 2: tree-sum fold partials -> us ----
    {
        float s0 = 0.f, s1 = 0.f;
        #pragma unroll
        for (int c = 0; c < 8; c += 2) { s0 += qs8[c][t]; s1 += qs8[c + 1][t]; }
        us[t] = s0 + s1;
    }
    __syncthreads();

    // ---- phase 3: scores — 16 threads/row, 15-shfl butterfly, exp ----
    {
        float s[NH];
        #pragma unroll
        for (int h = 0; h < NH; h++) {
            float4 u4 = ((const float4*)us)[h * 16 + u];
            s[h] = u4.x * x4.x + u4.y * x4.y + u4.z * x4.z + u4.w * x4.w;
        }
        #pragma unroll
        for (int h = 0; h < NH; h++)                // xor 8: full combine
            s[h] += __shfl_xor_sync(0xffffffffu, s[h], 8);
        float r4[4];
        {
            const bool lo = (u & 4) == 0;
            #pragma unroll
            for (int i = 0; i < 4; i++) {
                float give = lo ? s[i + 4] : s[i];
                float got  = __shfl_xor_sync(0xffffffffu, give, 4);
                r4[i] = (lo ? s[i] : s[i + 4]) + got;
            }
        }
        float r2[2];
        {
            const bool lo = (u & 2) == 0;
            #pragma unroll
            for (int i = 0; i < 2; i++) {
                float give = lo ? r4[i + 2] : r4[i];
                float got  = __shfl_xor_sync(0xffffffffu, give, 2);
                r2[i] = (lo ? r4[i] : r4[i + 2]) + got;
            }
        }
        float rf;
        {
            const bool lo = (u & 1) == 0;
            float give = lo ? r2[1] : r2[0];
            float got  = __shfl_xor_sync(0xffffffffu, give, 1);
            rf = (lo ? r2[0] : r2[1]) + got;
        }
        if (u < NH) es[g * 8 + u] = __expf(rf + cs[u]);
    }
    __syncthreads();

    // ---- phase 4: q partial (f-parallel, 8 j-lanes, float4 es reads) ----
    {
        const int f = t & 63, l = t >> 6;
        float acc[NH];
        #pragma unroll
        for (int h = 0; h < NH; h++) acc[h] = 0.f;
        #pragma unroll
        for (int jj = l; jj < RPB; jj += 8) {
            float4 e0 = ((const float4*)&es[jj * 8])[0];
            float4 e1 = ((const float4*)&es[jj * 8])[1];
            float xv = xs[jj * 68 + f];
            acc[0] += e0.x * xv; acc[1] += e0.y * xv;
            acc[2] += e0.z * xv; acc[3] += e0.w * xv;
            acc[4] += e1.x * xv; acc[5] += e1.y * xv;
            acc[6] += e1.z * xv; acc[7] += e1.w * xv;
        }
        #pragma unroll
        for (int h = 0; h < NH; h++) qs8[l][h * 64 + f] = acc[h];
    }
    __syncthreads();

    // ---- phase 5: float4 tree-sum + VECTOR RED publish (128 threads, v4) ----
    if (t < 128) {
        float4 a = make_float4(0.f, 0.f, 0.f, 0.f);
        #pragma unroll
        for (int c = 0; c < 8; c++) {
            float4 v = ((const float4*)qs8[c])[t];   // conflict-free LDS.128
            a.x += v.x; a.y += v.y; a.z += v.z; a.w += v.w;
        }
        red_add_v4(g_q + t * 4, a);
    } else if (t >= 128 && t < 128 + NH) {
        const int h = t - 128;
        float z0 = 0.f, z1 = 0.f, z2 = 0.f, z3 = 0.f;
        #pragma unroll
        for (int jj = 0; jj < RPB; jj += 4) {
            z0 += es[(jj + 0) * 8 + h];
            z1 += es[(jj + 1) * 8 + h];
            z2 += es[(jj + 2) * 8 + h];
            z3 += es[(jj + 3) * 8 + h];
        }
        atomicAdd(&g_Z[h], (z0 + z1) + (z2 + z3));
    }

    // ---- grid sync; stage W2/b2 inside the poll window ----
    __threadfence();
    __syncthreads();
    if (t == 0) atomicAdd(&g_arrive, 1);
    ((float4*)W2s)[t] = ((const float4*)W2)[t];
    if (t < NH) ((float4*)b2s)[t] = ((const float4*)b2)[t];
    if (t == 0) {
        while (*(volatile unsigned*)&g_arrive < NBLK) __nanosleep(32);
    }
    __syncthreads();
    __threadfence();

    // ---- tail (R6 lean structure) ----
    {
        const int f = t >> 3, h = t & 7;
        float v = g_q[h * 64 + f] / g_Z[h];
        v += __shfl_xor_sync(0xffffffffu, v, 1);
        v += __shfl_xor_sync(0xffffffffu, v, 2);
        v += __shfl_xor_sync(0xffffffffu, v, 4);
        if (h == 0) qbar[f] = v * (1.f / NH);
    }
    __syncthreads();
    if (t == 0) s_last = (atomicAdd(&g_exit, 1) == NBLK - 1);  // g_q consumed

    {   // os[m] = elu(lrelu(W1s[m,:].qbar + b1[m])) : 8 threads/output
        const int m = t >> 3, kc = t & 7;
        const float* wr = &W1s[m * 65 + kc * 8];
        const float* q8 = &qbar[kc * 8];
        float s = wr[0] * q8[0] + wr[1] * q8[1] + wr[2] * q8[2] + wr[3] * q8[3]
                + wr[4] * q8[4] + wr[5] * q8[5] + wr[6] * q8[6] + wr[7] * q8[7];
        s += __shfl_xor_sync(0xffffffffu, s, 1);
        s += __shfl_xor_sync(0xffffffffu, s, 2);
        s += __shfl_xor_sync(0xffffffffu, s, 4);
        if (kc == 0) {
            s += b1s[m];
            float lr = s > 0.f ? s : 0.2f * s;
            os[m] = lr > 0.f ? lr : (__expf(lr) - 1.f);
        }
    }
    __syncthreads();
    {   // fs[m] = lrelu(W2s[m,:].os + b2[m]) : 16 threads/output
        const int m = t >> 4, kc = t & 15;
        float4 w = ((const float4*)W2s)[m * 16 + kc];
        const float* o4 = &os[kc * 4];
        float s = w.x * o4[0] + w.y * o4[1] + w.z * o4[2] + w.w * o4[3];
        s += __shfl_xor_sync(0xffffffffu, s, 1);
        s += __shfl_xor_sync(0xffffffffu, s, 2);
        s += __shfl_xor_sync(0xffffffffu, s, 4);
        s += __shfl_xor_sync(0xffffffffu, s, 8);
        if (kc == 0) {
            s += b2s[m];
            fs[m] = s > 0.f ? s : 0.2f * s;
        }
    }
    __syncthreads();

    // ---- output: 32 rows x 32 cols per block = 256 float4 ----
    if (t < 256) {
        int f0 = (t & 7) << 2;
        float4 v = make_float4(fs[f0], fs[f0 + 1], fs[f0 + 2], fs[f0 + 3]);
        ((float4*)out)[b * 256 + t] = v;
    }

    // ---- reset for next graph replay (last exiting block; all reads done) ----
    __syncthreads();
    if (s_last) {
        g_q[t] = 0.f;
        if (t < NH) g_Z[t] = 0.f;
        if (t == 0) { g_arrive = 0; g_exit = 0; }
    }
}

extern "C" void kernel_launch(void* const* d_in, const int* in_sizes, int n_in,
                              void* d_out, int out_size) {
    const float* x   = (const float*)d_in[0];
    const float* W1  = (const float*)d_in[1];
    const float* b1  = (const float*)d_in[2];
    const float* a1w = (const float*)d_in[3];
    const float* a1b = (const float*)d_in[4];
    const float* W2  = (const float*)d_in[5];
    const float* b2  = (const float*)d_in[6];
    // d_in[7] (a2_w), d_in[8] (a2_b): provably no effect on output.

    gat_fused<<<NBLK, NT>>>(x, W1, b1, a1w, a1b, W2, b2, (float*)d_out);
}

// round 16
// speedup vs baseline: 1.2179x; 1.0328x over previous
#include <cuda_runtime.h>

// GAT_28295244546247 — v14: v10 base (best measured, 10.75us) with two
// straggler trims: (1) cs[h] computed by threads 448-511 in phase 0 from
// global (overlapped with staging latency) instead of riding on warp 0's
// fold; (2) tight volatile poll (no __nanosleep wake latency).
// Analytic collapse (R0): softmax row-constant cancels => identical output rows;
// layer2 softmax exactly uniform; a2_w/a2_b have no effect.

#define NH    8
#define NBLK  128
#define RPB   32
#define NT    512
#define F_OUT 32

__device__ float    g_q[NH * 64];   // zero-init; reset by last exiter each replay
__device__ float    g_Z[NH];
__device__ unsigned g_arrive = 0;
__device__ unsigned g_exit   = 0;

__global__ __launch_bounds__(NT) void gat_fused(
    const float* __restrict__ x,   const float* __restrict__ W1,
    const float* __restrict__ b1,  const float* __restrict__ a1w,
    const float* __restrict__ a1b, const float* __restrict__ W2,
    const float* __restrict__ b2,  float* __restrict__ out)
{
    __shared__ float W1s[64 * 65];                  // padded, conflict-free both axes
    __shared__ __align__(16) float W2s[F_OUT * 64];
    __shared__ __align__(16) float a1wjs[NH * 64];  // a1w[:,64:128]
    __shared__ __align__(16) float b1s[64];
    __shared__ __align__(16) float b2s[F_OUT];
    __shared__ __align__(16) float us[NH * 64];     // folded u [h][k]
    __shared__ float cs[NH];
    __shared__ __align__(16) float xs[RPB * 68];    // stride 68: float4-aligned rows
    __shared__ __align__(16) float es[RPB * NH];
    __shared__ float qs8[8][NH * 64];               // 8-copy partials (fold & q-accum)
    __shared__ float qbar[64];
    __shared__ float os[64];
    __shared__ float fs[F_OUT];
    __shared__ int   s_last;

    const int t = threadIdx.x;
    const int b = blockIdx.x;
    const int g = t >> 4, u = t & 15;               // 32 rows x 16 threads/row

    // ---- phase 0: x load + weight staging + cs (warps 14-15, from global) ----
    float4 x4 = ((const float4*)(x + (b * RPB + g) * 64 + u * 4))[0];
    {
        const float4* w4 = (const float4*)W1;
        #pragma unroll
        for (int r = 0; r < 2; r++) {
            int i = t + r * NT;
            float4 v = w4[i];
            int f = i >> 4, k = (i & 15) << 2;
            float* d = &W1s[f * 65 + k];
            d[0] = v.x; d[1] = v.y; d[2] = v.z; d[3] = v.w;
        }
        if (t < 128) {
            int h = t >> 4, q = t & 15;
            ((float4*)a1wjs)[h * 16 + q] = ((const float4*)a1w)[h * 32 + 16 + q];
        } else if (t < 144) {
            ((float4*)b1s)[t - 128] = ((const float4*)b1)[t - 128];
        }
        ((float4*)&xs[g * 68])[u] = x4;
    }
    // cs[h] = a1b[h] + a1wj[h].b1 : threads 448-511, 8 lanes/head, global reads
    // (latency overlaps the staging loads these threads already issued)
    if (t >= 448) {
        const int h = (t - 448) >> 3, part = t & 7;
        const int q0 = part * 2;                     // two float4s of the f-range
        float4 a0 = ((const float4*)a1w)[h * 32 + 16 + q0];
        float4 a1 = ((const float4*)a1w)[h * 32 + 16 + q0 + 1];
        float4 c0 = ((const float4*)b1)[q0];
        float4 c1 = ((const float4*)b1)[q0 + 1];
        float s = a0.x * c0.x + a0.y * c0.y + a0.z * c0.z + a0.w * c0.w
                + a1.x * c1.x + a1.y * c1.y + a1.z * c1.z + a1.w * c1.w;
        s += __shfl_xor_sync(0xffffffffu, s, 1);
        s += __shfl_xor_sync(0xffffffffu, s, 2);
        s += __shfl_xor_sync(0xffffffffu, s, 4);
        if (part == 0) cs[h] = s + a1b[h];
    }
    __syncthreads();

    // ---- phase 1: fold v2 — each W1s value read ONCE, shared across 8 heads ----
    {
        const int fg = t >> 6, k = t & 63;
        float acc[NH];
        #pragma unroll
        for (int h = 0; h < NH; h++) acc[h] = 0.f;
        #pragma unroll
        for (int q = 0; q < 2; q++) {               // two f-quads
            const int f0 = fg * 8 + q * 4;
            float4 ar[NH];                           // broadcast LDS.128 per head
            #pragma unroll
            for (int h = 0; h < NH; h++)
                ar[h] = ((const float4*)&a1wjs[h * 64 + f0])[0];
            #pragma unroll
            for (int fo = 0; fo < 4; fo++) {
                float w = W1s[(f0 + fo) * 65 + k];
                #pragma unroll
                for (int h = 0; h < NH; h++) {
                    float a = (fo == 0) ? ar[h].x : (fo == 1) ? ar[h].y
                            : (fo == 2) ? ar[h].z : ar[h].w;
                    acc[h] += w * a;
                }
            }
        }
        #pragma unroll
        for (int h = 0; h < NH; h++) qs8[fg][h * 64 + k] = acc[h];
    }
    __syncthreads();

    // ---- phase 2: tree-sum fold partials -> us ----
    {
        float s0 = 0.f, s1 = 0.f;
        #pragma unroll
        for (int c = 0; c < 8; c += 2) { s0 += qs8[c][t]; s1 += qs8[c + 1][t]; }
        us[t] = s0 + s1;
    }
    __syncthreads();

    // ---- phase 3: scores — 16 threads/row, 15-shfl butterfly, exp ----
    {
        float s[NH];
        #pragma unroll
        for (int h = 0; h < NH; h++) {
            float4 u4 = ((const float4*)us)[h * 16 + u];
            s[h] = u4.x * x4.x + u4.y * x4.y + u4.z * x4.z + u4.w * x4.w;
        }
        #pragma unroll
        for (int h = 0; h < NH; h++)                // xor 8: full combine
            s[h] += __shfl_xor_sync(0xffffffffu, s[h], 8);
        float r4[4];
        {
            const bool lo = (u & 4) == 0;
            #pragma unroll
            for (int i = 0; i < 4; i++) {
                float give = lo ? s[i + 4] : s[i];
                float got  = __shfl_xor_sync(0xffffffffu, give, 4);
                r4[i] = (lo ? s[i] : s[i + 4]) + got;
            }
        }
        float r2[2];
        {
            const bool lo = (u & 2) == 0;
            #pragma unroll
            for (int i = 0; i < 2; i++) {
                float give = lo ? r4[i + 2] : r4[i];
                float got  = __shfl_xor_sync(0xffffffffu, give, 2);
                r2[i] = (lo ? r4[i] : r4[i + 2]) + got;
            }
        }
        float rf;
        {
            const bool lo = (u & 1) == 0;
            float give = lo ? r2[1] : r2[0];
            float got  = __shfl_xor_sync(0xffffffffu, give, 1);
            rf = (lo ? r2[0] : r2[1]) + got;
        }
        if (u < NH) es[g * 8 + u] = __expf(rf + cs[u]);
    }
    __syncthreads();

    // ---- phase 4: q partial (f-parallel, 8 j-lanes, float4 es reads) ----
    {
        const int f = t & 63, l = t >> 6;
        float acc[NH];
        #pragma unroll
        for (int h = 0; h < NH; h++) acc[h] = 0.f;
        #pragma unroll
        for (int jj = l; jj < RPB; jj += 8) {
            float4 e0 = ((const float4*)&es[jj * 8])[0];
            float4 e1 = ((const float4*)&es[jj * 8])[1];
            float xv = xs[jj * 68 + f];
            acc[0] += e0.x * xv; acc[1] += e0.y * xv;
            acc[2] += e0.z * xv; acc[3] += e0.w * xv;
            acc[4] += e1.x * xv; acc[5] += e1.y * xv;
            acc[6] += e1.z * xv; acc[7] += e1.w * xv;
        }
        #pragma unroll
        for (int h = 0; h < NH; h++) qs8[l][h * 64 + f] = acc[h];
    }
    __syncthreads();

    // ---- phase 5: tree-sum + scalar RED publish (v10 form, measured best) ----
    {
        float s0 = 0.f, s1 = 0.f;
        #pragma unroll
        for (int c = 0; c < 8; c += 2) { s0 += qs8[c][t]; s1 += qs8[c + 1][t]; }
        atomicAdd(&g_q[t], s0 + s1);
    }
    if (t < NH) {
        float z0 = 0.f, z1 = 0.f, z2 = 0.f, z3 = 0.f;
        #pragma unroll
        for (int jj = 0; jj < RPB; jj += 4) {
            z0 += es[(jj + 0) * 8 + t];
            z1 += es[(jj + 1) * 8 + t];
            z2 += es[(jj + 2) * 8 + t];
            z3 += es[(jj + 3) * 8 + t];
        }
        atomicAdd(&g_Z[t], (z0 + z1) + (z2 + z3));
    }

    // ---- grid sync; stage W2/b2 inside the poll window; tight poll ----
    __threadfence();
    __syncthreads();
    if (t == 0) atomicAdd(&g_arrive, 1);
    ((float4*)W2s)[t] = ((const float4*)W2)[t];
    if (t < NH) ((float4*)b2s)[t] = ((const float4*)b2)[t];
    if (t == 0) {
        while (*(volatile unsigned*)&g_arrive < NBLK) { }   // tight spin, no sleep
    }
    __syncthreads();
    __threadfence();

    // ---- tail (R6 lean structure) ----
    {
        const int f = t >> 3, h = t & 7;
        float v = g_q[h * 64 + f] / g_Z[h];
        v += __shfl_xor_sync(0xffffffffu, v, 1);
        v += __shfl_xor_sync(0xffffffffu, v, 2);
        v += __shfl_xor_sync(0xffffffffu, v, 4);
        if (h == 0) qbar[f] = v * (1.f / NH);
    }
    __syncthreads();
    if (t == 0) s_last = (atomicAdd(&g_exit, 1) == NBLK - 1);  // g_q consumed

    {   // os[m] = elu(lrelu(W1s[m,:].qbar + b1[m])) : 8 threads/output
        const int m = t >> 3, kc = t & 7;
        const float* wr = &W1s[m * 65 + kc * 8];
        const float* q8 = &qbar[kc * 8];
        float s = wr[0] * q8[0] + wr[1] * q8[1] + wr[2] * q8[2] + wr[3] * q8[3]
                + wr[4] * q8[4] + wr[5] * q8[5] + wr[6] * q8[6] + wr[7] * q8[7];
        s += __shfl_xor_sync(0xffffffffu, s, 1);
        s += __shfl_xor_sync(0xffffffffu, s, 2);
        s += __shfl_xor_sync(0xffffffffu, s, 4);
        if (kc == 0) {
            s += b1s[m];
            float lr = s > 0.f ? s : 0.2f * s;
            os[m] = lr > 0.f ? lr : (__expf(lr) - 1.f);
        }
    }
    __syncthreads();
    {   // fs[m] = lrelu(W2s[m,:].os + b2[m]) : 16 threads/output
        const int m = t >> 4, kc = t & 15;
        float4 w = ((const float4*)W2s)[m * 16 + kc];
        const float* o4 = &os[kc * 4];
        float s = w.x * o4[0] + w.y * o4[1] + w.z * o4[2] + w.w * o4[3];
        s += __shfl_xor_sync(0xffffffffu, s, 1);
        s += __shfl_xor_sync(0xffffffffu, s, 2);
        s += __shfl_xor_sync(0xffffffffu, s, 4);
        s += __shfl_xor_sync(0xffffffffu, s, 8);
        if (kc == 0) {
            s += b2s[m];
            fs[m] = s > 0.f ? s : 0.2f * s;
        }
    }
    __syncthreads();

    // ---- output: 32 rows x 32 cols per block = 256 float4 ----
    if (t < 256) {
        int f0 = (t & 7) << 2;
        float4 v = make_float4(fs[f0], fs[f0 + 1], fs[f0 + 2], fs[f0 + 3]);
        ((float4*)out)[b * 256 + t] = v;
    }

    // ---- reset for next graph replay (last exiting block; all reads done) ----
    __syncthreads();
    if (s_last) {
        g_q[t] = 0.f;
        if (t < NH) g_Z[t] = 0.f;
        if (t == 0) { g_arrive = 0; g_exit = 0; }
    }
}

extern "C" void kernel_launch(void* const* d_in, const int* in_sizes, int n_in,
                              void* d_out, int out_size) {
    const float* x   = (const float*)d_in[0];
    const float* W1  = (const float*)d_in[1];
    const float* b1  = (const float*)d_in[2];
    const float* a1w = (const float*)d_in[3];
    const float* a1b = (const float*)d_in[4];
    const float* W2  = (const float*)d_in[5];
    const float* b2  = (const float*)d_in[6];
    // d_in[7] (a2_w), d_in[8] (a2_b): provably no effect on output.

    gat_fused<<<NBLK, NT>>>(x, W1, b1, a1w, a1b, W2, b2, (float*)d_out);
}